// round 3
// baseline (speedup 1.0000x reference)
#include <cuda_runtime.h>
#include <math.h>
#include <float.h>

// Shapes (fixed by the problem): z_e [32,64,64,64] f32, emb [512,64] f32.
#define N_TOK    131072      // B*H*W
#define K_CODES  512
#define D_DIM    64
#define HW       4096
// Output layout: concatenated reference tuple, all float32:
//   z_q_st [32,64,64,64] | loss_vq | perplexity | codes_used | usage_ratio | avg_dist2 | indices [32,64,64]
#define OFF_ZQ    0
#define OFF_SCAL  8388608
#define OFF_IDX   8388613

// Scratch (static device globals: allocation-free).
__device__ float        g_embpair[K_CODES * D_DIM];  // pair-interleaved: [(k>>1)][d][k&1]
__device__ float        g_bnorm[K_CODES];
__device__ int          g_idx[N_TOK];
__device__ unsigned int g_counts[K_CODES];
__device__ double       g_dsum;

// ---- packed f32x2 helpers (Blackwell-only packed fp32 pipe) ----
__device__ __forceinline__ unsigned long long fma2(unsigned long long a,
                                                   unsigned long long b,
                                                   unsigned long long c) {
    unsigned long long d;
    asm("fma.rn.f32x2 %0, %1, %2, %3;" : "=l"(d) : "l"(a), "l"(b), "l"(c));
    return d;
}
__device__ __forceinline__ unsigned long long add2(unsigned long long a,
                                                   unsigned long long b) {
    unsigned long long d;
    asm("add.rn.f32x2 %0, %1, %2;" : "=l"(d) : "l"(a), "l"(b));
    return d;
}
__device__ __forceinline__ unsigned long long dupf(float v) {
    unsigned long long d;
    unsigned int u = __float_as_uint(v);
    asm("mov.b64 %0, {%1, %1};" : "=l"(d) : "r"(u));
    return d;
}

// ---- prep: code norms + pair-interleaved emb layout + zero accumulators ----
__global__ void vq_prep(const float* __restrict__ emb) {
    int k = threadIdx.x;
    if (k < K_CODES) {
        const float* e = emb + k * D_DIM;
        float s = 0.f;
#pragma unroll
        for (int d = 0; d < D_DIM; ++d) {
            float v = e[d];
            s = fmaf(v, v, s);
            g_embpair[(((k >> 1) * D_DIM) + d) * 2 + (k & 1)] = v;
        }
        g_bnorm[k]  = s;
        g_counts[k] = 0u;
    }
    if (threadIdx.x == 0) g_dsum = 0.0;
}

// ---- main: argmin over 512 codes per token, f32x2 code-paired FMA ----
__global__ __launch_bounds__(256, 1)
void vq_main(const float* __restrict__ z_e, float* __restrict__ out) {
    extern __shared__ __align__(16) float sm[];
    float*        s_embp = sm;                    // 32768 floats (128 KB)
    float*        s_bn   = sm + 32768;            // 512 floats
    unsigned int* s_hist = (unsigned int*)(sm + 32768 + 512);  // 512 u32

    {
        const float4* gp = (const float4*)g_embpair;
        float4*       sp = (float4*)s_embp;
        for (int i = threadIdx.x; i < 8192; i += 256) sp[i] = gp[i];
        for (int i = threadIdx.x; i < 512; i += 256) {
            s_bn[i]   = g_bnorm[i];
            s_hist[i] = 0u;
        }
    }
    __syncthreads();

    const int n = blockIdx.x * 256 + threadIdx.x;          // token id
    const float* zp = z_e + ((size_t)(n >> 12) << 18) + (n & (HW - 1));

    // Load token (coalesced per-d across the warp), compute A=||z||^2,
    // and duplicate each z[d] into both f32x2 lanes.
    unsigned long long zz[64];
    float a0 = 0.f, a1 = 0.f, a2 = 0.f, a3 = 0.f;
#pragma unroll
    for (int d = 0; d < 64; d += 4) {
        float v0 = zp[(size_t)(d + 0) << 12];
        float v1 = zp[(size_t)(d + 1) << 12];
        float v2 = zp[(size_t)(d + 2) << 12];
        float v3 = zp[(size_t)(d + 3) << 12];
        a0 = fmaf(v0, v0, a0);
        a1 = fmaf(v1, v1, a1);
        a2 = fmaf(v2, v2, a2);
        a3 = fmaf(v3, v3, a3);
        zz[d + 0] = dupf(v0);
        zz[d + 1] = dupf(v1);
        zz[d + 2] = dupf(v2);
        zz[d + 3] = dupf(v3);
    }
    const float A = (a0 + a1) + (a2 + a3);

    float dmin = FLT_MAX;
    int   imin = 0;
#pragma unroll 1
    for (int p = 0; p < 256; ++p) {
        const ulonglong2* row = (const ulonglong2*)(s_embp + (p << 7));
        unsigned long long acc0 = 0ull, acc1 = 0ull, acc2 = 0ull, acc3 = 0ull;
#pragma unroll
        for (int j = 0; j < 32; j += 2) {
            ulonglong2 q0 = row[j];
            ulonglong2 q1 = row[j + 1];
            acc0 = fma2(zz[2 * j + 0], q0.x, acc0);
            acc1 = fma2(zz[2 * j + 1], q0.y, acc1);
            acc2 = fma2(zz[2 * j + 2], q1.x, acc2);
            acc3 = fma2(zz[2 * j + 3], q1.y, acc3);
        }
        unsigned long long s = add2(add2(acc0, acc1), add2(acc2, acc3));
        float dot0 = __uint_as_float((unsigned int)(s & 0xffffffffull));
        float dot1 = __uint_as_float((unsigned int)(s >> 32));
        // Replicate reference rounding: d = fl( fl(A + B) - 2*dot )
        float d0 = fmaf(dot0, -2.f, A + s_bn[2 * p]);
        float d1 = fmaf(dot1, -2.f, A + s_bn[2 * p + 1]);
        if (d0 < dmin) { dmin = d0; imin = 2 * p; }
        if (d1 < dmin) { dmin = d1; imin = 2 * p + 1; }
    }

    g_idx[n]           = imin;
    out[OFF_IDX + n]   = (float)imin;
    atomicAdd(&s_hist[imin], 1u);

    // sum of min distances (== N*avg_dist2; loss_vq = 1.25*avg_dist2)
    float v = dmin;
#pragma unroll
    for (int o = 16; o; o >>= 1) v += __shfl_xor_sync(0xffffffffu, v, o);
    if ((threadIdx.x & 31) == 0) atomicAdd(&g_dsum, (double)v);

    __syncthreads();
    for (int i = threadIdx.x; i < 512; i += 256) {
        unsigned int c = s_hist[i];
        if (c) atomicAdd(&g_counts[i], c);
    }
}

// ---- z_q scatter: out[b,d,h,w] = emb[idx[b,h,w], d] (emb stays L1-resident) ----
__global__ void vq_zq(const float* __restrict__ emb, float* __restrict__ out) {
    int t  = blockIdx.x * 256 + threadIdx.x;   // 2,097,152 threads, 4 d's each
    int hw = t & (HW - 1);
    int d4 = (t >> 12) & 15;
    int b  = t >> 16;
    int idx = g_idx[(b << 12) + hw];
    const float4 e = *(const float4*)(emb + idx * 64 + d4 * 4);
    int base = (b << 18) + (d4 << 14) + hw;
    out[base        ] = e.x;
    out[base +  4096] = e.y;
    out[base +  8192] = e.z;
    out[base + 12288] = e.w;
}

// ---- scalars: entropy/perplexity/usage + losses ----
__global__ void vq_finalize(float* __restrict__ out) {
    __shared__ double s_e[16];
    __shared__ int    s_u[16];
    int k = threadIdx.x;
    unsigned int c = g_counts[k];
    double p = (double)c * (1.0 / 131072.0);
    double e = (c > 0) ? -p * log(p) : 0.0;
    int    u = (c > 0) ? 1 : 0;
#pragma unroll
    for (int o = 16; o; o >>= 1) {
        e += __shfl_xor_sync(0xffffffffu, e, o);
        u += __shfl_xor_sync(0xffffffffu, u, o);
    }
    if ((k & 31) == 0) { s_e[k >> 5] = e; s_u[k >> 5] = u; }
    __syncthreads();
    if (k == 0) {
        double ent = 0.0; int used = 0;
        for (int i = 0; i < 16; ++i) { ent += s_e[i]; used += s_u[i]; }
        double avg = g_dsum * (1.0 / 131072.0);
        out[OFF_SCAL + 0] = (float)(1.25 * avg);        // loss_vq
        out[OFF_SCAL + 1] = (float)exp(ent);            // perplexity
        out[OFF_SCAL + 2] = (float)used;                // codes_used
        out[OFF_SCAL + 3] = (float)used / 512.0f;       // usage_ratio
        out[OFF_SCAL + 4] = (float)avg;                 // avg_dist2
    }
}

extern "C" void kernel_launch(void* const* d_in, const int* in_sizes, int n_in,
                              void* d_out, int out_size) {
    const float* z_e = (const float*)d_in[0];
    const float* emb = (const float*)d_in[1];
    float*       out = (float*)d_out;

    const int smem_bytes = (32768 + 512) * 4 + 512 * 4;  // 135168 B
    cudaFuncSetAttribute(vq_main, cudaFuncAttributeMaxDynamicSharedMemorySize,
                         smem_bytes);

    vq_prep<<<1, 512>>>(emb);
    vq_main<<<N_TOK / 256, 256, smem_bytes>>>(z_e, out);
    vq_zq<<<(N_TOK * D_DIM / 4) / 256, 256>>>(emb, out);
    vq_finalize<<<1, 512>>>(out);
}

// round 4
// speedup vs baseline: 1.0005x; 1.0005x over previous
#include <cuda_runtime.h>
#include <math.h>
#include <float.h>

// Shapes (fixed by the problem): z_e [32,64,64,64] f32, emb [512,64] f32.
#define N_TOK    131072      // B*H*W
#define K_CODES  512
#define D_DIM    64
#define HW       4096
// Output layout: concatenated reference tuple, all float32:
//   z_q_st [32,64,64,64] | loss_vq | perplexity | codes_used | usage_ratio | avg_dist2 | indices [32,64,64]
#define OFF_ZQ    0
#define OFF_SCAL  8388608
#define OFF_IDX   8388613

// Scratch (static device globals: allocation-free).
__device__ float        g_embpair[K_CODES * D_DIM];  // pair-interleaved: [(k>>1)][d][k&1]
__device__ float        g_bnorm[K_CODES];
__device__ int          g_idx[N_TOK];
__device__ unsigned int g_counts[K_CODES];
__device__ double       g_dsum;

// ---- packed f32x2 helpers (Blackwell-only packed fp32 pipe) ----
__device__ __forceinline__ unsigned long long fma2(unsigned long long a,
                                                   unsigned long long b,
                                                   unsigned long long c) {
    unsigned long long d;
    asm("fma.rn.f32x2 %0, %1, %2, %3;" : "=l"(d) : "l"(a), "l"(b), "l"(c));
    return d;
}
__device__ __forceinline__ unsigned long long add2(unsigned long long a,
                                                   unsigned long long b) {
    unsigned long long d;
    asm("add.rn.f32x2 %0, %1, %2;" : "=l"(d) : "l"(a), "l"(b));
    return d;
}
__device__ __forceinline__ unsigned long long dupf(float v) {
    unsigned long long d;
    unsigned int u = __float_as_uint(v);
    asm("mov.b64 %0, {%1, %1};" : "=l"(d) : "r"(u));
    return d;
}

// ---- prep: code norms + pair-interleaved emb layout + zero accumulators ----
__global__ void vq_prep(const float* __restrict__ emb) {
    int k = threadIdx.x;
    if (k < K_CODES) {
        const float* e = emb + k * D_DIM;
        float s = 0.f;
#pragma unroll
        for (int d = 0; d < D_DIM; ++d) {
            float v = e[d];
            s = fmaf(v, v, s);
            g_embpair[(((k >> 1) * D_DIM) + d) * 2 + (k & 1)] = v;
        }
        g_bnorm[k]  = s;
        g_counts[k] = 0u;
    }
    if (threadIdx.x == 0) g_dsum = 0.0;
}

// ---- main: argmin over 512 codes per token, f32x2 code-paired FMA ----
__global__ __launch_bounds__(256, 1)
void vq_main(const float* __restrict__ z_e, float* __restrict__ out) {
    extern __shared__ __align__(16) float sm[];
    float*        s_embp = sm;                    // 32768 floats (128 KB)
    float*        s_bn   = sm + 32768;            // 512 floats
    unsigned int* s_hist = (unsigned int*)(sm + 32768 + 512);  // 512 u32

    {
        const float4* gp = (const float4*)g_embpair;
        float4*       sp = (float4*)s_embp;
        for (int i = threadIdx.x; i < 8192; i += 256) sp[i] = gp[i];
        for (int i = threadIdx.x; i < 512; i += 256) {
            s_bn[i]   = g_bnorm[i];
            s_hist[i] = 0u;
        }
    }
    __syncthreads();

    const int n = blockIdx.x * 256 + threadIdx.x;          // token id
    const float* zp = z_e + ((size_t)(n >> 12) << 18) + (n & (HW - 1));

    // Load token (coalesced per-d across the warp), compute A=||z||^2,
    // and duplicate each z[d] into both f32x2 lanes.
    unsigned long long zz[64];
    float a0 = 0.f, a1 = 0.f, a2 = 0.f, a3 = 0.f;
#pragma unroll
    for (int d = 0; d < 64; d += 4) {
        float v0 = zp[(size_t)(d + 0) << 12];
        float v1 = zp[(size_t)(d + 1) << 12];
        float v2 = zp[(size_t)(d + 2) << 12];
        float v3 = zp[(size_t)(d + 3) << 12];
        a0 = fmaf(v0, v0, a0);
        a1 = fmaf(v1, v1, a1);
        a2 = fmaf(v2, v2, a2);
        a3 = fmaf(v3, v3, a3);
        zz[d + 0] = dupf(v0);
        zz[d + 1] = dupf(v1);
        zz[d + 2] = dupf(v2);
        zz[d + 3] = dupf(v3);
    }
    const float A = (a0 + a1) + (a2 + a3);

    float dmin = FLT_MAX;
    int   imin = 0;
#pragma unroll 1
    for (int p = 0; p < 256; ++p) {
        const ulonglong2* row = (const ulonglong2*)(s_embp + (p << 7));
        unsigned long long acc0 = 0ull, acc1 = 0ull, acc2 = 0ull, acc3 = 0ull;
#pragma unroll
        for (int j = 0; j < 32; j += 2) {
            ulonglong2 q0 = row[j];
            ulonglong2 q1 = row[j + 1];
            acc0 = fma2(zz[2 * j + 0], q0.x, acc0);
            acc1 = fma2(zz[2 * j + 1], q0.y, acc1);
            acc2 = fma2(zz[2 * j + 2], q1.x, acc2);
            acc3 = fma2(zz[2 * j + 3], q1.y, acc3);
        }
        unsigned long long s = add2(add2(acc0, acc1), add2(acc2, acc3));
        float dot0 = __uint_as_float((unsigned int)(s & 0xffffffffull));
        float dot1 = __uint_as_float((unsigned int)(s >> 32));
        // Replicate reference rounding: d = fl( fl(A + B) - 2*dot )
        float d0 = fmaf(dot0, -2.f, A + s_bn[2 * p]);
        float d1 = fmaf(dot1, -2.f, A + s_bn[2 * p + 1]);
        if (d0 < dmin) { dmin = d0; imin = 2 * p; }
        if (d1 < dmin) { dmin = d1; imin = 2 * p + 1; }
    }

    g_idx[n]           = imin;
    out[OFF_IDX + n]   = (float)imin;
    atomicAdd(&s_hist[imin], 1u);

    // sum of min distances (== N*avg_dist2; loss_vq = 1.25*avg_dist2)
    float v = dmin;
#pragma unroll
    for (int o = 16; o; o >>= 1) v += __shfl_xor_sync(0xffffffffu, v, o);
    if ((threadIdx.x & 31) == 0) atomicAdd(&g_dsum, (double)v);

    __syncthreads();
    for (int i = threadIdx.x; i < 512; i += 256) {
        unsigned int c = s_hist[i];
        if (c) atomicAdd(&g_counts[i], c);
    }
}

// ---- z_q scatter: out[b,d,h,w] = emb[idx[b,h,w], d] (emb stays L1-resident) ----
__global__ void vq_zq(const float* __restrict__ emb, float* __restrict__ out) {
    int t  = blockIdx.x * 256 + threadIdx.x;   // 2,097,152 threads, 4 d's each
    int hw = t & (HW - 1);
    int d4 = (t >> 12) & 15;
    int b  = t >> 16;
    int idx = g_idx[(b << 12) + hw];
    const float4 e = *(const float4*)(emb + idx * 64 + d4 * 4);
    int base = (b << 18) + (d4 << 14) + hw;
    out[base        ] = e.x;
    out[base +  4096] = e.y;
    out[base +  8192] = e.z;
    out[base + 12288] = e.w;
}

// ---- scalars: entropy/perplexity/usage + losses ----
__global__ void vq_finalize(float* __restrict__ out) {
    __shared__ double s_e[16];
    __shared__ int    s_u[16];
    int k = threadIdx.x;
    unsigned int c = g_counts[k];
    double p = (double)c * (1.0 / 131072.0);
    double e = (c > 0) ? -p * log(p) : 0.0;
    int    u = (c > 0) ? 1 : 0;
#pragma unroll
    for (int o = 16; o; o >>= 1) {
        e += __shfl_xor_sync(0xffffffffu, e, o);
        u += __shfl_xor_sync(0xffffffffu, u, o);
    }
    if ((k & 31) == 0) { s_e[k >> 5] = e; s_u[k >> 5] = u; }
    __syncthreads();
    if (k == 0) {
        double ent = 0.0; int used = 0;
        for (int i = 0; i < 16; ++i) { ent += s_e[i]; used += s_u[i]; }
        double avg = g_dsum * (1.0 / 131072.0);
        out[OFF_SCAL + 0] = (float)(1.25 * avg);        // loss_vq
        out[OFF_SCAL + 1] = (float)exp(ent);            // perplexity
        out[OFF_SCAL + 2] = (float)used;                // codes_used
        out[OFF_SCAL + 3] = (float)used / 512.0f;       // usage_ratio
        out[OFF_SCAL + 4] = (float)avg;                 // avg_dist2
    }
}

extern "C" void kernel_launch(void* const* d_in, const int* in_sizes, int n_in,
                              void* d_out, int out_size) {
    const float* z_e = (const float*)d_in[0];
    const float* emb = (const float*)d_in[1];
    float*       out = (float*)d_out;

    const int smem_bytes = (32768 + 512) * 4 + 512 * 4;  // 135168 B
    cudaFuncSetAttribute(vq_main, cudaFuncAttributeMaxDynamicSharedMemorySize,
                         smem_bytes);

    vq_prep<<<1, 512>>>(emb);
    vq_main<<<N_TOK / 256, 256, smem_bytes>>>(z_e, out);
    vq_zq<<<(N_TOK * D_DIM / 4) / 256, 256>>>(emb, out);
    vq_finalize<<<1, 512>>>(out);
}

// round 5
// speedup vs baseline: 1.4687x; 1.4680x over previous
#include <cuda_runtime.h>
#include <math.h>
#include <float.h>

// Shapes (fixed): z_e [32,64,64,64] f32, emb [512,64] f32.
#define N_TOK    131072      // B*H*W
#define K_CODES  512
#define D_DIM    64
#define HW       4096
// Output: z_q_st [32,64,64,64] | loss_vq | perplexity | codes_used | usage_ratio | avg_dist2 | indices [32,64,64]
#define OFF_ZQ    0
#define OFF_SCAL  8388608
#define OFF_IDX   8388613

// Scratch (static device globals: allocation-free).
__device__ float        g_bnorm[K_CODES];
__device__ int          g_idx[N_TOK];
__device__ unsigned int g_counts[K_CODES];
__device__ double       g_dsum;

typedef unsigned long long ull;

// ---- packed f32x2 helpers (Blackwell packed fp32 pipe) ----
__device__ __forceinline__ ull fma2(ull a, ull b, ull c) {
    ull d;
    asm("fma.rn.f32x2 %0, %1, %2, %3;" : "=l"(d) : "l"(a), "l"(b), "l"(c));
    return d;
}
__device__ __forceinline__ ull add2(ull a, ull b) {
    ull d;
    asm("add.rn.f32x2 %0, %1, %2;" : "=l"(d) : "l"(a), "l"(b));
    return d;
}
__device__ __forceinline__ ull pack2(float lo, float hi) {
    ull d;
    asm("mov.b64 %0, {%1, %2};" : "=l"(d) : "f"(lo), "f"(hi));
    return d;
}
__device__ __forceinline__ float lanesum(ull s) {
    float lo, hi;
    asm("mov.b64 {%0, %1}, %2;" : "=f"(lo), "=f"(hi) : "l"(s));
    return lo + hi;
}

// ---- prep: code norms + zero accumulators ----
__global__ void vq_prep(const float* __restrict__ emb) {
    int k = threadIdx.x;
    if (k < K_CODES) {
        const float* e = emb + k * D_DIM;
        float s = 0.f;
#pragma unroll
        for (int d = 0; d < D_DIM; ++d) s = fmaf(e[d], e[d], s);
        g_bnorm[k]  = s;
        g_counts[k] = 0u;
    }
    if (threadIdx.x == 0) g_dsum = 0.0;
}

// ---- main: 2 tokens/thread, z d-pair-packed in f32x2 lanes, emb row reused ----
__global__ __launch_bounds__(256, 1)
void vq_main(const float* __restrict__ z_e, const float* __restrict__ emb,
             float* __restrict__ out) {
    extern __shared__ __align__(16) float sm[];
    float*        s_emb  = sm;                                  // 32768 floats (128 KB)
    float*        s_bn   = sm + 32768;                          // 512 floats
    unsigned int* s_hist = (unsigned int*)(sm + 32768 + 512);   // 512 u32

    {
        const float4* gp = (const float4*)emb;
        float4*       sp = (float4*)s_emb;
        for (int i = threadIdx.x; i < 8192; i += 256) sp[i] = gp[i];
        for (int i = threadIdx.x; i < 512; i += 256) {
            s_bn[i]   = g_bnorm[i];
            s_hist[i] = 0u;
        }
    }
    __syncthreads();

    // Tokens: n0 = base + tid, n1 = n0 + 256 (both warp-coalesced in hw dim).
    const int n0 = blockIdx.x * 512 + threadIdx.x;
    const int n1 = n0 + 256;
    const float* zp0 = z_e + ((size_t)(n0 >> 12) << 18) + (n0 & (HW - 1));
    const float* zp1 = z_e + ((size_t)(n1 >> 12) << 18) + (n1 & (HW - 1));

    // Load both tokens, pack consecutive-d pairs into f32x2 lanes,
    // and compute A = ||z||^2 per token.
    ull z0[32], z1[32];
    float a00 = 0.f, a01 = 0.f, a10 = 0.f, a11 = 0.f;
#pragma unroll
    for (int j = 0; j < 32; j += 2) {
        float u0 = zp0[(size_t)(2 * j + 0) << 12];
        float u1 = zp0[(size_t)(2 * j + 1) << 12];
        float u2 = zp0[(size_t)(2 * j + 2) << 12];
        float u3 = zp0[(size_t)(2 * j + 3) << 12];
        float v0 = zp1[(size_t)(2 * j + 0) << 12];
        float v1 = zp1[(size_t)(2 * j + 1) << 12];
        float v2 = zp1[(size_t)(2 * j + 2) << 12];
        float v3 = zp1[(size_t)(2 * j + 3) << 12];
        a00 = fmaf(u0, u0, a00); a00 = fmaf(u1, u1, a00);
        a01 = fmaf(u2, u2, a01); a01 = fmaf(u3, u3, a01);
        a10 = fmaf(v0, v0, a10); a10 = fmaf(v1, v1, a10);
        a11 = fmaf(v2, v2, a11); a11 = fmaf(v3, v3, a11);
        z0[j]     = pack2(u0, u1);
        z0[j + 1] = pack2(u2, u3);
        z1[j]     = pack2(v0, v1);
        z1[j + 1] = pack2(v2, v3);
    }
    const float A0 = a00 + a01;
    const float A1 = a10 + a11;

    float dmin0 = FLT_MAX, dmin1 = FLT_MAX;
    int   imin0 = 0,       imin1 = 0;
#pragma unroll 1
    for (int k = 0; k < K_CODES; ++k) {
        const ulonglong2* row = (const ulonglong2*)(s_emb + (k << 6));
        ull c00 = 0ull, c01 = 0ull, c10 = 0ull, c11 = 0ull;
#pragma unroll
        for (int j = 0; j < 16; j += 2) {
            ulonglong2 q0 = row[j];        // d-pairs 2j, 2j+1
            ulonglong2 q1 = row[j + 1];    // d-pairs 2j+2, 2j+3
            c00 = fma2(z0[2 * j + 0], q0.x, c00);
            c10 = fma2(z1[2 * j + 0], q0.x, c10);
            c01 = fma2(z0[2 * j + 1], q0.y, c01);
            c11 = fma2(z1[2 * j + 1], q0.y, c11);
            c00 = fma2(z0[2 * j + 2], q1.x, c00);
            c10 = fma2(z1[2 * j + 2], q1.x, c10);
            c01 = fma2(z0[2 * j + 3], q1.y, c01);
            c11 = fma2(z1[2 * j + 3], q1.y, c11);
        }
        float bn   = s_bn[k];
        float dot0 = lanesum(add2(c00, c01));
        float dot1 = lanesum(add2(c10, c11));
        float d0   = fmaf(dot0, -2.f, A0 + bn);
        float d1   = fmaf(dot1, -2.f, A1 + bn);
        if (d0 < dmin0) { dmin0 = d0; imin0 = k; }
        if (d1 < dmin1) { dmin1 = d1; imin1 = k; }
    }

    g_idx[n0]         = imin0;
    g_idx[n1]         = imin1;
    out[OFF_IDX + n0] = (float)imin0;
    out[OFF_IDX + n1] = (float)imin1;
    atomicAdd(&s_hist[imin0], 1u);
    atomicAdd(&s_hist[imin1], 1u);

    // sum of min distances (== N*avg_dist2; loss_vq = 1.25*avg_dist2)
    float v = dmin0 + dmin1;
#pragma unroll
    for (int o = 16; o; o >>= 1) v += __shfl_xor_sync(0xffffffffu, v, o);
    if ((threadIdx.x & 31) == 0) atomicAdd(&g_dsum, (double)v);

    __syncthreads();
    for (int i = threadIdx.x; i < 512; i += 256) {
        unsigned int c = s_hist[i];
        if (c) atomicAdd(&g_counts[i], c);
    }
}

// ---- z_q scatter: out[b,d,h,w] = emb[idx[b,h,w], d] (emb stays cache-resident) ----
__global__ void vq_zq(const float* __restrict__ emb, float* __restrict__ out) {
    int t  = blockIdx.x * 256 + threadIdx.x;   // 2,097,152 threads, 4 d's each
    int hw = t & (HW - 1);
    int d4 = (t >> 12) & 15;
    int b  = t >> 16;
    int idx = g_idx[(b << 12) + hw];
    const float4 e = *(const float4*)(emb + idx * 64 + d4 * 4);
    int base = (b << 18) + (d4 << 14) + hw;
    out[base        ] = e.x;
    out[base +  4096] = e.y;
    out[base +  8192] = e.z;
    out[base + 12288] = e.w;
}

// ---- scalars: entropy/perplexity/usage + losses (fp32 math, fp64 only for sums) ----
__global__ void vq_finalize(float* __restrict__ out) {
    __shared__ float s_e[16];
    __shared__ int   s_u[16];
    int k = threadIdx.x;
    unsigned int c = g_counts[k];
    float p = (float)c * (1.0f / 131072.0f);
    float e = (c > 0) ? -p * logf(p) : 0.0f;
    int   u = (c > 0) ? 1 : 0;
#pragma unroll
    for (int o = 16; o; o >>= 1) {
        e += __shfl_xor_sync(0xffffffffu, e, o);
        u += __shfl_xor_sync(0xffffffffu, u, o);
    }
    if ((k & 31) == 0) { s_e[k >> 5] = e; s_u[k >> 5] = u; }
    __syncthreads();
    if (k == 0) {
        float ent = 0.0f; int used = 0;
        for (int i = 0; i < 16; ++i) { ent += s_e[i]; used += s_u[i]; }
        float avg = (float)(g_dsum * (1.0 / 131072.0));
        out[OFF_SCAL + 0] = 1.25f * avg;                // loss_vq
        out[OFF_SCAL + 1] = expf(ent);                  // perplexity
        out[OFF_SCAL + 2] = (float)used;                // codes_used
        out[OFF_SCAL + 3] = (float)used / 512.0f;       // usage_ratio
        out[OFF_SCAL + 4] = avg;                        // avg_dist2
    }
}

extern "C" void kernel_launch(void* const* d_in, const int* in_sizes, int n_in,
                              void* d_out, int out_size) {
    const float* z_e = (const float*)d_in[0];
    const float* emb = (const float*)d_in[1];
    float*       out = (float*)d_out;

    const int smem_bytes = (32768 + 512) * 4 + 512 * 4;  // 135168 B
    cudaFuncSetAttribute(vq_main, cudaFuncAttributeMaxDynamicSharedMemorySize,
                         smem_bytes);

    vq_prep<<<1, 512>>>(emb);
    vq_main<<<N_TOK / 512, 256, smem_bytes>>>(z_e, emb, out);
    vq_zq<<<(N_TOK * D_DIM / 4) / 256, 256>>>(emb, out);
    vq_finalize<<<1, 512>>>(out);
}